// round 11
// baseline (speedup 1.0000x reference)
#include <cuda_runtime.h>
#include <cuda_bf16.h>

#define NN   50
#define NN2  2500          // N*N
#define ATT  4000          // alpha steps / t-range
#define BB   512           // batch
#define PP   32            // features p
#define NP   (BB * PP)     // 16384 (b,p) pairs
#define CAP  32            // per-t slot capacity (P(overflow) ~ 1e-18)

// Scratch (static __device__ globals: allocation-free rule)
__device__ float g_F[NN2];                   // F = g @ w^2
__device__ float g_fT[(size_t)ATT * NN2];    // fT[t][j][i] (i fastest, 50-wide)
__device__ int   g_cnt[ATT];                 // per-t pair count (ticket counter)
__device__ int   g_slot[ATT * CAP];          // pair indices per t
__device__ float g_xT[(size_t)BB * PP * NN]; // xT[b][p][i] (i contiguous)

// ---------------------------------------------------------------------------
// Kernel A (grid 625 x 128): WARP-PER-ROW matvec. 4 warps = 4 rows per block;
// w^2 staged in smem once per block (single barrier), then each lane streams
// ~20 independent float4 g loads with 4 accumulators — high MLP, reduction is
// shuffle-only (no block barriers in the hot path). Folds Z init + cnt zero.
// ---------------------------------------------------------------------------
__global__ void __launch_bounds__(128) kA_F(
        const float* __restrict__ g, const float* __restrict__ w,
        float* __restrict__ outF,
        const int* __restrict__ y_i, const float* __restrict__ mus,
        float* __restrict__ Z) {
    int tid = threadIdx.x;
    int gid = blockIdx.x * 128 + tid;   // 80000 threads

    if (gid < BB * NN) {
        int b = gid / NN, i = gid - b * NN;
        Z[gid] = (float)PP * mus[(size_t)y_i[b] * NN + i];
    } else if (gid < BB * NN + ATT) {
        g_cnt[gid - BB * NN] = 0;
    }

    __shared__ float4 w2s[640];          // 625 used (10 KB)

    const float4* w4 = (const float4*)w;
    for (int c = tid; c < NN2 / 4; c += 128) {
        float4 wv = w4[c];
        w2s[c] = make_float4(wv.x * wv.x, wv.y * wv.y, wv.z * wv.z, wv.w * wv.w);
    }
    __syncthreads();

    int wid  = tid >> 5;
    int lane = tid & 31;
    int row  = blockIdx.x * 4 + wid;     // 625*4 = 2500, exact

    const float4* grow = (const float4*)(g + (size_t)row * NN2);  // 625 float4

    float s0 = 0.f, s1 = 0.f, s2 = 0.f, s3 = 0.f;
    #pragma unroll 5
    for (int k = 0; k < 20; k++) {
        int c = lane + (k << 5);
        if (c < NN2 / 4) {
            float4 gv = grow[c];
            float4 wv = w2s[c];
            // rotate accumulators to keep 4 independent FMA chains
            if ((k & 3) == 0)      s0 += gv.x*wv.x + gv.y*wv.y + gv.z*wv.z + gv.w*wv.w;
            else if ((k & 3) == 1) s1 += gv.x*wv.x + gv.y*wv.y + gv.z*wv.z + gv.w*wv.w;
            else if ((k & 3) == 2) s2 += gv.x*wv.x + gv.y*wv.y + gv.z*wv.z + gv.w*wv.w;
            else                   s3 += gv.x*wv.x + gv.y*wv.y + gv.z*wv.z + gv.w*wv.w;
        }
    }
    float s = (s0 + s1) + (s2 + s3);
    #pragma unroll
    for (int o = 16; o; o >>= 1) s += __shfl_down_sync(0xffffffffu, s, o);
    if (lane == 0) { g_F[row] = s; outF[row] = s; }
}

// ---------------------------------------------------------------------------
// Kernel T (grid 512 x 256): standalone coalesced x->xT transpose via smem.
// ---------------------------------------------------------------------------
__global__ void kT(const float* __restrict__ x) {
    __shared__ float tile[NN * PP];
    int b = blockIdx.x;
    const float* src = x + (size_t)b * (NN * PP);
    for (int o = threadIdx.x; o < NN * PP; o += 256)
        tile[o] = src[o];                           // coalesced (p fastest)
    __syncthreads();
    float* dst = g_xT + (size_t)b * (PP * NN);
    for (int o = threadIdx.x; o < PP * NN; o += 256) {
        int p = o / NN, i = o - p * NN;
        dst[o] = tile[i * PP + p];                  // coalesced writes
    }
}

// ---------------------------------------------------------------------------
// Kernel B (grid 1000 x 256): softmax table, 4 t per block, 64 threads per t.
// Folds in hist+scatter ONLY (ticket = atomicAdd doubles as slot index).
// ---------------------------------------------------------------------------
__global__ void kB_softmaxT(const float* __restrict__ alphas,
                            const int* __restrict__ x_i) {
    int gid = blockIdx.x * 256 + threadIdx.x;
    if (gid < NP) {
        int t = x_i[gid];
        int ticket = atomicAdd(&g_cnt[t], 1);
        if (ticket < CAP) g_slot[t * CAP + ticket] = gid;
    }

    __shared__ float Fs[NN2];
    for (int idx = threadIdx.x; idx < NN2; idx += 256)
        Fs[idx] = g_F[idx];
    __syncthreads();

    int lt = threadIdx.x >> 6;        // 0..3
    int i  = threadIdx.x & 63;        // row index
    int t  = (blockIdx.x << 2) + lt;
    if (i >= NN) return;

    float a = alphas[t];
    float e[NN];
    float s = 0.f;
    #pragma unroll
    for (int j = 0; j < NN; j++) {
        float v = __expf(-a * Fs[i * NN + j]);
        e[j] = v;
        s += v;
    }
    float rinv = __fdividef(1.0f, s);
    float* dst = g_fT + (size_t)t * NN2 + i;
    #pragma unroll
    for (int j = 0; j < NN; j++)
        dst[j * NN] = e[j] * rinv;
}

// ---------------------------------------------------------------------------
// Kernel C2 (grid 4000 x 64): one block per t. Loads fT[t] row into registers
// ONCE (thread i holds f[i][0..49]) and applies it to all pairs with this t,
// 4 pairs per pass from smem. Table traffic: 40MB instead of 164MB.
// ---------------------------------------------------------------------------
__global__ void kC2(const float* __restrict__ mus, float* __restrict__ Z) {
    int t = blockIdx.x;
    int cnt = g_cnt[t];
    if (cnt == 0) return;
    if (cnt > CAP) cnt = CAP;

    int i = threadIdx.x;              // 0..63, active < 50
    __shared__ float a_s[4][NN + 2];

    float freg[NN];
    float mu_i = 0.f;
    if (i < NN) {
        mu_i = mus[(size_t)t * NN + i];
        const float* fr = g_fT + (size_t)t * NN2 + i;
        #pragma unroll
        for (int j = 0; j < NN; j++) freg[j] = fr[j * NN];
    }

    for (int base = 0; base < cnt; base += 4) {
        if (i < NN) {
            #pragma unroll
            for (int k = 0; k < 4; k++) {
                int q = base + k;
                int pr = (q < cnt) ? g_slot[t * CAP + q] : 0;
                a_s[k][i] = g_xT[(size_t)pr * NN + i] - mu_i;
            }
        }
        __syncthreads();
        if (i < NN) {
            float acc0 = 0.f, acc1 = 0.f, acc2 = 0.f, acc3 = 0.f;
            #pragma unroll
            for (int j = 0; j < NN; j++) {
                float f = freg[j];
                acc0 += f * a_s[0][j];
                acc1 += f * a_s[1][j];
                acc2 += f * a_s[2][j];
                acc3 += f * a_s[3][j];
            }
            float acc[4] = {acc0, acc1, acc2, acc3};
            #pragma unroll
            for (int k = 0; k < 4; k++) {
                int q = base + k;
                if (q < cnt) {
                    int pr = g_slot[t * CAP + q];
                    int b = pr >> 5;
                    atomicAdd(&Z[b * NN + i], acc[k]);
                }
            }
        }
        __syncthreads();
    }
}

// ---------------------------------------------------------------------------
extern "C" void kernel_launch(void* const* d_in, const int* in_sizes, int n_in,
                              void* d_out, int out_size) {
    const float* x      = (const float*)d_in[0];   // [512,50,32]
    const int*   x_i    = (const int*)  d_in[1];   // [512,32]
    const int*   y_i    = (const int*)  d_in[2];   // [512]
    const float* g      = (const float*)d_in[3];   // [2500,2500]
    const float* w      = (const float*)d_in[4];   // [2500,1]
    const float* mus    = (const float*)d_in[5];   // [4000,50]
    const float* alphas = (const float*)d_in[6];   // [4000,1]

    float* Z    = (float*)d_out;        // [512*50]
    float* outF = Z + BB * NN;          // [2500]

    kA_F<<<625, 128>>>(g, w, outF, y_i, mus, Z);
    kT<<<BB, 256>>>(x);
    kB_softmaxT<<<ATT / 4, 256>>>(alphas, x_i);
    kC2<<<ATT, 64>>>(mus, Z);
}

// round 12
// speedup vs baseline: 1.3711x; 1.3711x over previous
#include <cuda_runtime.h>
#include <cuda_bf16.h>

#define NN   50
#define NN2  2500          // N*N
#define ATT  4000          // alpha steps / t-range
#define BB   512           // batch
#define PP   32            // features p
#define NP   (BB * PP)     // 16384 (b,p) pairs
#define CAP  32            // per-t slot capacity (P(overflow) ~ 1e-18)

// Scratch (static __device__ globals: allocation-free rule)
__device__ float g_F[NN2];                   // F = g @ w^2
__device__ int   g_cnt[ATT];                 // per-t pair count (zero-init; self-cleaned by kBC)
__device__ int   g_slot[ATT * CAP];          // pair indices per t
__device__ float g_xT[(size_t)BB * PP * NN]; // xT[b][p][i] (i contiguous)

// ---------------------------------------------------------------------------
// Kernel A (grid 625 x 256): FOUR rows per block; w^2 staged in smem once and
// amortized over 4 row-streams (4 independent LDG.128 per column group).
// Folds in: Z init and the hist+scatter (ticket = atomicAdd doubles as slot
// index; g_cnt enters zeroed because kBC cleans it at the end of each call).
// ---------------------------------------------------------------------------
__global__ void kA_F(const float* __restrict__ g, const float* __restrict__ w,
                     float* __restrict__ outF,
                     const int* __restrict__ y_i, const float* __restrict__ mus,
                     const int* __restrict__ x_i, float* __restrict__ Z) {
    int tid = threadIdx.x;
    int gid = blockIdx.x * 256 + tid;   // 160000 threads

    if (gid < BB * NN) {
        int b = gid / NN, i = gid - b * NN;
        Z[gid] = (float)PP * mus[(size_t)y_i[b] * NN + i];
    }
    if (gid < NP) {
        int t = x_i[gid];
        int ticket = atomicAdd(&g_cnt[t], 1);
        if (ticket < CAP) g_slot[t * CAP + ticket] = gid;
    }

    __shared__ float4 w2s[640];          // 625 used (10 KB)
    __shared__ float  red[4][8];

    const float4* w4 = (const float4*)w;
    for (int c = tid; c < NN2 / 4; c += 256) {
        float4 wv = w4[c];
        w2s[c] = make_float4(wv.x * wv.x, wv.y * wv.y, wv.z * wv.z, wv.w * wv.w);
    }
    __syncthreads();

    int row0 = blockIdx.x * 4;
    const float4* gr0 = (const float4*)(g + (size_t)(row0 + 0) * NN2);
    const float4* gr1 = (const float4*)(g + (size_t)(row0 + 1) * NN2);
    const float4* gr2 = (const float4*)(g + (size_t)(row0 + 2) * NN2);
    const float4* gr3 = (const float4*)(g + (size_t)(row0 + 3) * NN2);

    float s0 = 0.f, s1 = 0.f, s2 = 0.f, s3 = 0.f;
    #pragma unroll
    for (int cg = 0; cg < 3; cg++) {
        int c = tid + cg * 256;
        if (c < NN2 / 4) {
            float4 wv = w2s[c];
            float4 a = gr0[c];
            float4 b = gr1[c];
            float4 d = gr2[c];
            float4 e = gr3[c];
            s0 += a.x * wv.x + a.y * wv.y + a.z * wv.z + a.w * wv.w;
            s1 += b.x * wv.x + b.y * wv.y + b.z * wv.z + b.w * wv.w;
            s2 += d.x * wv.x + d.y * wv.y + d.z * wv.z + d.w * wv.w;
            s3 += e.x * wv.x + e.y * wv.y + e.z * wv.z + e.w * wv.w;
        }
    }

    #pragma unroll
    for (int o = 16; o; o >>= 1) {
        s0 += __shfl_down_sync(0xffffffffu, s0, o);
        s1 += __shfl_down_sync(0xffffffffu, s1, o);
        s2 += __shfl_down_sync(0xffffffffu, s2, o);
        s3 += __shfl_down_sync(0xffffffffu, s3, o);
    }
    int lane = tid & 31, wid = tid >> 5;
    if (lane == 0) {
        red[0][wid] = s0; red[1][wid] = s1; red[2][wid] = s2; red[3][wid] = s3;
    }
    __syncthreads();
    if (tid < 32) {
        int r = tid >> 3, wx = tid & 7;
        float v = red[r][wx];
        v += __shfl_down_sync(0xffffffffu, v, 4, 8);
        v += __shfl_down_sync(0xffffffffu, v, 2, 8);
        v += __shfl_down_sync(0xffffffffu, v, 1, 8);
        if (wx == 0) { g_F[row0 + r] = v; outF[row0 + r] = v; }
    }
}

// ---------------------------------------------------------------------------
// Kernel T (grid 512 x 256): standalone coalesced x->xT transpose via smem.
// ---------------------------------------------------------------------------
__global__ void kT(const float* __restrict__ x) {
    __shared__ float tile[NN * PP];
    int b = blockIdx.x;
    const float* src = x + (size_t)b * (NN * PP);
    for (int o = threadIdx.x; o < NN * PP; o += 256)
        tile[o] = src[o];                           // coalesced (p fastest)
    __syncthreads();
    float* dst = g_xT + (size_t)b * (PP * NN);
    for (int o = threadIdx.x; o < PP * NN; o += 256) {
        int p = o / NN, i = o - p * NN;
        dst[o] = tile[i * PP + p];                  // coalesced writes
    }
}

// ---------------------------------------------------------------------------
// Kernel BC (grid 4000 x 64): FUSED softmax + apply. One block per t:
//   - skip if no pairs (cnt==0, ~1.7% of blocks)
//   - compute eT[j*50+i] = exp(-a*F[i*50+j]) in smem (10 KB; NO global table)
//   - rinv[i] = 1/row-sum
//   - apply to this t's pairs, 4 per pass (kC2's proven structure; eT via LDS)
//   - self-clean g_cnt[t] = 0 for the next graph replay
// Deletes the 40MB fT store + 40MB read (~13us of DRAM traffic) and a launch.
// ---------------------------------------------------------------------------
__global__ void kBC(const float* __restrict__ mus, const float* __restrict__ alphas,
                    float* __restrict__ Z) {
    int t = blockIdx.x;
    int cnt = g_cnt[t];
    if (cnt == 0) return;
    if (cnt > CAP) cnt = CAP;

    int tid = threadIdx.x;            // 0..63
    __shared__ float eT[NN2];         // eT[j*50+i]
    __shared__ float rinv_s[NN];
    __shared__ float a_s[4][NN + 2];

    float a = alphas[t];
    // exp phase: 2500 elements, 64 threads, coalesced g_F reads (L2-resident 10KB)
    for (int idx = tid; idx < NN2; idx += 64) {
        int i = idx / NN, j = idx - i * NN;
        eT[j * NN + i] = __expf(-a * g_F[idx]);
    }
    __syncthreads();

    if (tid < NN) {
        float s = 0.f;
        #pragma unroll
        for (int j = 0; j < NN; j++) s += eT[j * NN + tid];   // conflict-free
        rinv_s[tid] = __fdividef(1.0f, s);
    }
    __syncthreads();

    int i = tid;                      // active < 50
    float mu_i = 0.f, rv = 0.f;
    if (i < NN) {
        mu_i = mus[(size_t)t * NN + i];
        rv = rinv_s[i];
    }

    for (int base = 0; base < cnt; base += 4) {
        if (i < NN) {
            #pragma unroll
            for (int k = 0; k < 4; k++) {
                int q = base + k;
                int pr = (q < cnt) ? g_slot[t * CAP + q] : 0;
                a_s[k][i] = g_xT[(size_t)pr * NN + i] - mu_i;
            }
        }
        __syncthreads();
        if (i < NN) {
            float acc0 = 0.f, acc1 = 0.f, acc2 = 0.f, acc3 = 0.f;
            #pragma unroll
            for (int j = 0; j < NN; j++) {
                float f = eT[j * NN + i];        // LDS, conflict-free across lanes
                acc0 += f * a_s[0][j];
                acc1 += f * a_s[1][j];
                acc2 += f * a_s[2][j];
                acc3 += f * a_s[3][j];
            }
            float acc[4] = {acc0, acc1, acc2, acc3};
            #pragma unroll
            for (int k = 0; k < 4; k++) {
                int q = base + k;
                if (q < cnt) {
                    int pr = g_slot[t * CAP + q];
                    int b = pr >> 5;
                    atomicAdd(&Z[b * NN + i], acc[k] * rv);
                }
            }
        }
        __syncthreads();
    }

    if (tid == 0) g_cnt[t] = 0;       // self-clean for next replay
}

// ---------------------------------------------------------------------------
extern "C" void kernel_launch(void* const* d_in, const int* in_sizes, int n_in,
                              void* d_out, int out_size) {
    const float* x      = (const float*)d_in[0];   // [512,50,32]
    const int*   x_i    = (const int*)  d_in[1];   // [512,32]
    const int*   y_i    = (const int*)  d_in[2];   // [512]
    const float* g      = (const float*)d_in[3];   // [2500,2500]
    const float* w      = (const float*)d_in[4];   // [2500,1]
    const float* mus    = (const float*)d_in[5];   // [4000,50]
    const float* alphas = (const float*)d_in[6];   // [4000,1]

    float* Z    = (float*)d_out;        // [512*50]
    float* outF = Z + BB * NN;          // [2500]

    kA_F<<<625, 256>>>(g, w, outF, y_i, mus, x_i, Z);
    kT<<<BB, 256>>>(x);
    kBC<<<ATT, 64>>>(mus, alphas, Z);
}

// round 13
// speedup vs baseline: 1.3992x; 1.0205x over previous
#include <cuda_runtime.h>
#include <cuda_bf16.h>

#define NN   50
#define NN2  2500          // N*N
#define ATT  4000          // alpha steps / t-range
#define BB   512           // batch
#define PP   32            // features p
#define NP   (BB * PP)     // 16384 (b,p) pairs
#define CAP  32            // per-t slot capacity (P(overflow) ~ 1e-18)

// Scratch (static __device__ globals: allocation-free rule)
__device__ float g_F[NN2];                   // F = g @ w^2
__device__ int   g_cnt[ATT];                 // per-t pair count (zero-init; self-cleaned by kBC)
__device__ int   g_slot[ATT * CAP];          // pair indices per t
__device__ float g_xT[(size_t)BB * PP * NN]; // xT[b][p][i] (i contiguous)

// ---------------------------------------------------------------------------
// Kernel A (grid 1250 x 256): TWO rows per block for full occupancy
// (regs=32 -> 8 blocks/SM; 1250/148 = 8.4 available). w^2 staged in smem once;
// each thread issues 6 batched LDG.128s (3 col-groups x 2 rows).
// Folds in: Z init and hist+scatter (ticket doubles as slot index).
// ---------------------------------------------------------------------------
__global__ void __launch_bounds__(256) kA_F(
        const float* __restrict__ g, const float* __restrict__ w,
        float* __restrict__ outF,
        const int* __restrict__ y_i, const float* __restrict__ mus,
        const int* __restrict__ x_i, float* __restrict__ Z) {
    int tid = threadIdx.x;
    int gid = blockIdx.x * 256 + tid;   // 320000 threads

    if (gid < BB * NN) {
        int b = gid / NN, i = gid - b * NN;
        Z[gid] = (float)PP * mus[(size_t)y_i[b] * NN + i];
    }
    if (gid < NP) {
        int t = x_i[gid];
        int ticket = atomicAdd(&g_cnt[t], 1);
        if (ticket < CAP) g_slot[t * CAP + ticket] = gid;
    }

    __shared__ float4 w2s[640];          // 625 used (10 KB)
    __shared__ float  red[2][8];

    const float4* w4 = (const float4*)w;
    for (int c = tid; c < NN2 / 4; c += 256) {
        float4 wv = w4[c];
        w2s[c] = make_float4(wv.x * wv.x, wv.y * wv.y, wv.z * wv.z, wv.w * wv.w);
    }
    __syncthreads();

    int row0 = blockIdx.x * 2;
    const float4* gr0 = (const float4*)(g + (size_t)(row0 + 0) * NN2);
    const float4* gr1 = (const float4*)(g + (size_t)(row0 + 1) * NN2);
    bool p2 = (tid < 625 - 512);         // tid < 113

    // Batched independent g loads (the only DRAM stream)
    float4 a0 = gr0[tid];
    float4 a1 = gr0[tid + 256];
    float4 a2 = p2 ? gr0[tid + 512] : make_float4(0.f, 0.f, 0.f, 0.f);
    float4 b0 = gr1[tid];
    float4 b1 = gr1[tid + 256];
    float4 b2 = p2 ? gr1[tid + 512] : make_float4(0.f, 0.f, 0.f, 0.f);

    float4 w0 = w2s[tid];
    float4 w1 = w2s[tid + 256];
    float4 w2 = p2 ? w2s[tid + 512] : make_float4(0.f, 0.f, 0.f, 0.f);

    float s0, s1;
    s0  = a0.x * w0.x + a0.y * w0.y + a0.z * w0.z + a0.w * w0.w;
    s0 += a1.x * w1.x + a1.y * w1.y + a1.z * w1.z + a1.w * w1.w;
    s0 += a2.x * w2.x + a2.y * w2.y + a2.z * w2.z + a2.w * w2.w;
    s1  = b0.x * w0.x + b0.y * w0.y + b0.z * w0.z + b0.w * w0.w;
    s1 += b1.x * w1.x + b1.y * w1.y + b1.z * w1.z + b1.w * w1.w;
    s1 += b2.x * w2.x + b2.y * w2.y + b2.z * w2.z + b2.w * w2.w;

    #pragma unroll
    for (int o = 16; o; o >>= 1) {
        s0 += __shfl_down_sync(0xffffffffu, s0, o);
        s1 += __shfl_down_sync(0xffffffffu, s1, o);
    }
    int lane = tid & 31, wid = tid >> 5;
    if (lane == 0) { red[0][wid] = s0; red[1][wid] = s1; }
    __syncthreads();
    if (tid < 16) {
        int r = tid >> 3, wx = tid & 7;
        float v = red[r][wx];
        v += __shfl_down_sync(0x0000ffffu, v, 4, 8);
        v += __shfl_down_sync(0x0000ffffu, v, 2, 8);
        v += __shfl_down_sync(0x0000ffffu, v, 1, 8);
        if (wx == 0) { g_F[row0 + r] = v; outF[row0 + r] = v; }
    }
}

// ---------------------------------------------------------------------------
// Kernel T (grid 512 x 256): standalone coalesced x->xT transpose via smem.
// ---------------------------------------------------------------------------
__global__ void kT(const float* __restrict__ x) {
    __shared__ float tile[NN * PP];
    int b = blockIdx.x;
    const float* src = x + (size_t)b * (NN * PP);
    for (int o = threadIdx.x; o < NN * PP; o += 256)
        tile[o] = src[o];                           // coalesced (p fastest)
    __syncthreads();
    float* dst = g_xT + (size_t)b * (PP * NN);
    for (int o = threadIdx.x; o < PP * NN; o += 256) {
        int p = o / NN, i = o - p * NN;
        dst[o] = tile[i * PP + p];                  // coalesced writes
    }
}

// ---------------------------------------------------------------------------
// Kernel BC (grid 4000 x 128): FUSED softmax + apply. One block per t:
//   - exp phase: g_F read as float4 (5 LDG.128/thread), eT built transposed
//     in smem. 128 threads halve the serial depth vs the 64-thread version.
//   - rinv[i] = 1/row-sum (conflict-free smem reads)
//   - apply to this t's pairs, 4 per pass (proven structure)
//   - self-clean g_cnt[t] = 0 for the next graph replay
// ---------------------------------------------------------------------------
__global__ void kBC(const float* __restrict__ mus, const float* __restrict__ alphas,
                    float* __restrict__ Z) {
    int t = blockIdx.x;
    int cnt = g_cnt[t];
    if (cnt == 0) return;
    if (cnt > CAP) cnt = CAP;

    int tid = threadIdx.x;            // 0..127
    __shared__ float eT[NN2];         // eT[j*50+i]
    __shared__ float rinv_s[NN];
    __shared__ float a_s[4][NN + 2];

    float a = alphas[t];
    const float4* F4 = (const float4*)g_F;    // 625 float4
    for (int c = tid; c < NN2 / 4; c += 128) {
        float4 fv = F4[c];
        int idx = c * 4;
        float v0 = __expf(-a * fv.x);
        float v1 = __expf(-a * fv.y);
        float v2 = __expf(-a * fv.z);
        float v3 = __expf(-a * fv.w);
        int i0 = (idx + 0) / NN, j0 = (idx + 0) - i0 * NN;
        int i1 = (idx + 1) / NN, j1 = (idx + 1) - i1 * NN;
        int i2 = (idx + 2) / NN, j2 = (idx + 2) - i2 * NN;
        int i3 = (idx + 3) / NN, j3 = (idx + 3) - i3 * NN;
        eT[j0 * NN + i0] = v0;
        eT[j1 * NN + i1] = v1;
        eT[j2 * NN + i2] = v2;
        eT[j3 * NN + i3] = v3;
    }
    __syncthreads();

    if (tid < NN) {
        float s = 0.f;
        #pragma unroll
        for (int j = 0; j < NN; j++) s += eT[j * NN + tid];   // conflict-free
        rinv_s[tid] = __fdividef(1.0f, s);
    }
    __syncthreads();

    int i = tid;                      // active < 50
    float mu_i = 0.f, rv = 0.f;
    if (i < NN) {
        mu_i = mus[(size_t)t * NN + i];
        rv = rinv_s[i];
    }

    for (int base = 0; base < cnt; base += 4) {
        if (i < NN) {
            #pragma unroll
            for (int k = 0; k < 4; k++) {
                int q = base + k;
                int pr = (q < cnt) ? g_slot[t * CAP + q] : 0;
                a_s[k][i] = g_xT[(size_t)pr * NN + i] - mu_i;
            }
        }
        __syncthreads();
        if (i < NN) {
            float acc0 = 0.f, acc1 = 0.f, acc2 = 0.f, acc3 = 0.f;
            #pragma unroll
            for (int j = 0; j < NN; j++) {
                float f = eT[j * NN + i];        // LDS, conflict-free across lanes
                acc0 += f * a_s[0][j];
                acc1 += f * a_s[1][j];
                acc2 += f * a_s[2][j];
                acc3 += f * a_s[3][j];
            }
            float acc[4] = {acc0, acc1, acc2, acc3};
            #pragma unroll
            for (int k = 0; k < 4; k++) {
                int q = base + k;
                if (q < cnt) {
                    int pr = g_slot[t * CAP + q];
                    int b = pr >> 5;
                    atomicAdd(&Z[b * NN + i], acc[k] * rv);
                }
            }
        }
        __syncthreads();
    }

    if (tid == 0) g_cnt[t] = 0;       // self-clean for next replay
}

// ---------------------------------------------------------------------------
extern "C" void kernel_launch(void* const* d_in, const int* in_sizes, int n_in,
                              void* d_out, int out_size) {
    const float* x      = (const float*)d_in[0];   // [512,50,32]
    const int*   x_i    = (const int*)  d_in[1];   // [512,32]
    const int*   y_i    = (const int*)  d_in[2];   // [512]
    const float* g      = (const float*)d_in[3];   // [2500,2500]
    const float* w      = (const float*)d_in[4];   // [2500,1]
    const float* mus    = (const float*)d_in[5];   // [4000,50]
    const float* alphas = (const float*)d_in[6];   // [4000,1]

    float* Z    = (float*)d_out;        // [512*50]
    float* outF = Z + BB * NN;          // [2500]

    kA_F<<<1250, 256>>>(g, w, outF, y_i, mus, x_i, Z);
    kT<<<BB, 256>>>(x);
    kBC<<<ATT, 128>>>(mus, alphas, Z);
}